// round 12
// baseline (speedup 1.0000x reference)
#include <cuda_runtime.h>
#include <math_constants.h>

// KNN min-dist, 9x9 window, C=3, zero-padded.
// d^2 = |t|^2 + (|o|^2 - 2 t.o). Pixel-pair f32x2: thread owns px cols
// (2tx, 2tx+1); shift dj needs obs cols (2tx+dj, 2tx+dj+1) -> one aligned
// ld.shared.b64 from parity-interleaved pair planes. Zero packs in loop.
// Fixed shapes: B=4, C=3, H=256, W=512.

#define B_ 4
#define H_ 256
#define W_ 512
#define HW_ (H_*W_)

#define TY 4
#define SH_H 40
#define SH_W 40
#define NE 20
#define NR 12
#define NITEMS (SH_H * 39)   // 1560 pair-build items

typedef unsigned long long u64;

__device__ __forceinline__ u64 pk2(float lo, float hi){
    u64 r; asm("mov.b64 %0, {%1,%2};" : "=l"(r) : "f"(lo), "f"(hi)); return r;
}
__device__ __forceinline__ void upk2(u64 v, float& lo, float& hi){
    asm("mov.b64 {%0,%1}, %2;" : "=f"(lo), "=f"(hi) : "l"(v));
}
__device__ __forceinline__ u64 fma2(u64 a, u64 b, u64 c){
    u64 r; asm("fma.rn.f32x2 %0, %1, %2, %3;" : "=l"(r) : "l"(a), "l"(b), "l"(c)); return r;
}

__global__ __launch_bounds__(128, 4) void knn_min_kernel(
    const float* __restrict__ tfm, const float* __restrict__ obs,
    float* __restrict__ out)
{
    // P[parity][channel][row][entry]: entry e of parity p = cols (2e+p, 2e+p+1)
    __shared__ float2 P[2][3][SH_H][NE];   // 38.4 KB
    __shared__ float  Q[SH_H][SH_W];       //  6.4 KB  (q = |o|^2, scalar)

    const int b  = blockIdx.z;
    const int x0 = blockIdx.x * 32;
    const int y0 = blockIdx.y * 32;
    const int tid = threadIdx.x;
    const int tx = tid & 15;
    const int ty = tid >> 4;

    const float* obs_b = obs + b * 3 * HW_;
    const float* tfm_b = tfm + b * 3 * HW_;

    // ---- tfm loads first (overlap with prologue) ----
    const int xb = x0 + 2 * tx;
    const int ybase = y0 + ty * TY;
    float2 ta[TY], tc[TY], te[TY];
#pragma unroll
    for (int k = 0; k < TY; k++) {
        int g = (ybase + k) * W_ + xb;
        ta[k] = *(const float2*)&tfm_b[g];
        tc[k] = *(const float2*)&tfm_b[HW_ + g];
        te[k] = *(const float2*)&tfm_b[2 * HW_ + g];
    }

    // ---- build pair planes + q plane directly from gmem ----
#pragma unroll 1
    for (int l = 0; l < 13; l++) {
        int idx = tid + l * 128;
        if (idx < NITEMS) {
            int r = idx / 39;
            int c = idx - r * 39;          // pair base col 0..38
            int gy = y0 - 4 + r;
            int gxa = x0 - 4 + c;
            bool rok = (gy >= 0) & (gy < H_);
            float a0 = 0.f, a1 = 0.f, a2 = 0.f;
            float c0 = 0.f, c1 = 0.f, c2 = 0.f;
            if (rok && gxa >= 0 && gxa < W_) {
                int g = gy * W_ + gxa;
                a0 = obs_b[g]; a1 = obs_b[HW_ + g]; a2 = obs_b[2 * HW_ + g];
            }
            if (rok && gxa + 1 >= 0 && gxa + 1 < W_) {
                int g = gy * W_ + gxa + 1;
                c0 = obs_b[g]; c1 = obs_b[HW_ + g]; c2 = obs_b[2 * HW_ + g];
            }
            int par = c & 1, e = c >> 1;
            P[par][0][r][e] = make_float2(a0, c0);
            P[par][1][r][e] = make_float2(a1, c1);
            P[par][2][r][e] = make_float2(a2, c2);
            Q[r][c] = fmaf(a2, a2, fmaf(a1, a1, a0 * a0));
            if (c == 38)
                Q[r][39] = fmaf(c2, c2, fmaf(c1, c1, c0 * c0));
        }
    }
    __syncthreads();

    // ---- per-pixel-pair constants ----
    u64 NT0[TY], NT1[TY], NT2[TY];
    float tt0[TY], tt1[TY], m0[TY], m1[TY];
#pragma unroll
    for (int k = 0; k < TY; k++) {
        NT0[k] = pk2(-2.f * ta[k].x, -2.f * ta[k].y);
        NT1[k] = pk2(-2.f * tc[k].x, -2.f * tc[k].y);
        NT2[k] = pk2(-2.f * te[k].x, -2.f * te[k].y);
        tt0[k] = fmaf(te[k].x, te[k].x, fmaf(tc[k].x, tc[k].x, ta[k].x * ta[k].x));
        tt1[k] = fmaf(te[k].y, te[k].y, fmaf(tc[k].y, tc[k].y, ta[k].y * ta[k].y));
        m0[k] = CUDART_INF_F;
        m1[k] = CUDART_INF_F;
    }

    const int rbase = ty * TY;

    // One dj pass. PAR: parity plane set; EE: entry idx; QC: q col (= 2tx+dj).
#define PASS(PAR, EE, QC, ODDQ)                                             \
    {                                                                       \
        const u64* p0 = (const u64*)&P[PAR][0][rbase][EE];                  \
        const u64* p1 = (const u64*)&P[PAR][1][rbase][EE];                  \
        const u64* p2 = (const u64*)&P[PAR][2][rbase][EE];                  \
        const float* pq = &Q[rbase][QC];                                    \
        _Pragma("unroll")                                                   \
        for (int r = 0; r < NR; r++) {                                      \
            u64 O0 = p0[r * NE];                                            \
            u64 O1 = p1[r * NE];                                            \
            u64 O2 = p2[r * NE];                                            \
            u64 QQ;                                                         \
            if (ODDQ) QQ = pk2(pq[r * SH_W], pq[r * SH_W + 1]);             \
            else      QQ = *(const u64*)&pq[r * SH_W];                      \
            _Pragma("unroll")                                               \
            for (int k = 0; k < TY; k++) {                                  \
                if (r >= k && r <= k + 8) {                                 \
                    u64 E = fma2(NT0[k], O0,                                \
                            fma2(NT1[k], O1,                                \
                            fma2(NT2[k], O2, QQ)));                         \
                    float elo, ehi;                                         \
                    upk2(E, elo, ehi);                                      \
                    m0[k] = fminf(m0[k], elo);                              \
                    m1[k] = fminf(m1[k], ehi);                              \
                }                                                           \
            }                                                               \
        }                                                                   \
    }

#pragma unroll 1
    for (int j = 0; j < 4; j++) {
        PASS(0, tx + j, 2 * tx + 2 * j, 0)       // dj = 2j   (even)
        PASS(1, tx + j, 2 * tx + 2 * j + 1, 1)   // dj = 2j+1 (odd)
    }
    PASS(0, tx + 4, 2 * tx + 8, 0)               // dj = 8

#undef PASS

    float* out_b = out + b * HW_;
#pragma unroll
    for (int k = 0; k < TY; k++) {
        float2 o;
        o.x = sqrtf(fmaxf(tt0[k] + m0[k], 0.f));
        o.y = sqrtf(fmaxf(tt1[k] + m1[k], 0.f));
        *(float2*)&out_b[(ybase + k) * W_ + xb] = o;
    }
}

extern "C" void kernel_launch(void* const* d_in, const int* in_sizes, int n_in,
                              void* d_out, int out_size)
{
    const float* tfm = (const float*)d_in[0];
    const float* obs = (const float*)d_in[1];
    float* out = (float*)d_out;
    (void)in_sizes; (void)n_in; (void)out_size;

    dim3 grid(W_ / 32, H_ / 32, B_);   // 16 x 8 x 4 = 512 blocks
    dim3 block(128);
    knn_min_kernel<<<grid, block>>>(tfm, obs, out);
}

// round 13
// speedup vs baseline: 1.4026x; 1.4026x over previous
#include <cuda_runtime.h>
#include <math_constants.h>

// KNN min-dist, 9x9 window, C=3, zero-padded.
// d^2 = |t|^2 + (|o|^2 - 2 t.o), q=|o|^2 in float4.w -> 3 FFMA + 1 FMNMX/shift.
// R7 mainloop (flat (dj,r) unroll, 2-deep lookahead, dual min acc) +
// MLP-batched prologue: tfm LDGs issued first, all 24 obs LDGs batched
// (one DRAM round), STS+q in a second phase. Fixed shapes: B=4,C=3,H=256,W=512.

#define BDIM 128
#define TW 32
#define TH 16
#define TY 4
#define HALO 4
#define SW 9

#define B_ 4
#define H_ 256
#define W_ 512
#define HW_ (H_*W_)

#define SH_H (TH + 2*HALO)   // 24
#define SH_W (TW + 2*HALO)   // 40
#define NR (TY + SW - 1)     // 12
#define NITER (SW * NR)      // 108
#define NELEM (SH_H * SH_W)  // 960

__global__ __launch_bounds__(BDIM, 7) void knn_min_kernel(
    const float* __restrict__ tfm, const float* __restrict__ obs,
    float* __restrict__ out)
{
    __shared__ float4 s4[SH_H][SH_W];   // (o0, o1, o2, |o|^2)

    const int b  = blockIdx.z;
    const int x0 = blockIdx.x * TW;
    const int y0 = blockIdx.y * TH;
    const int tid = threadIdx.x;
    const int tx = tid & 31;
    const int ty = tid >> 5;

    const float* obs_b = obs + b * 3 * HW_;
    const float* tfm_b = tfm + b * 3 * HW_;

    // ---- prologue: tfm LDGs first (longest dependence chain to mainloop) ----
    const int ybase = y0 + ty * TY;
    const int xg = x0 + tx;
    float ta[TY], tc[TY], te[TY];
#pragma unroll
    for (int k = 0; k < TY; k++) {
        int g = (ybase + k) * W_ + xg;
        ta[k] = tfm_b[g];
        tc[k] = tfm_b[HW_ + g];
        te[k] = tfm_b[2 * HW_ + g];
    }

    // ---- phase 1: batch ALL obs LDGs (idx = tid + l*BDIM; 960 < 8*128) ----
    float v0[8], v1[8], v2[8];
#pragma unroll
    for (int l = 0; l < 8; l++) {
        int idx = tid + l * BDIM;
        int iy = idx / SH_W;
        int ix = idx - iy * SH_W;
        int gy = y0 - HALO + iy;
        int gx = x0 - HALO + ix;
        bool ok = (idx < NELEM) & (gy >= 0) & (gy < H_) & (gx >= 0) & (gx < W_);
        int g = gy * W_ + gx;
        v0[l] = ok ? obs_b[g] : 0.f;
        v1[l] = ok ? obs_b[HW_ + g] : 0.f;
        v2[l] = ok ? obs_b[2 * HW_ + g] : 0.f;
    }
    // ---- phase 2: q + STS ----
#pragma unroll
    for (int l = 0; l < 8; l++) {
        int idx = tid + l * BDIM;
        if (idx < NELEM) {
            int iy = idx / SH_W;
            int ix = idx - iy * SH_W;
            float q = fmaf(v2[l], v2[l], fmaf(v1[l], v1[l], v0[l] * v0[l]));
            s4[iy][ix] = make_float4(v0[l], v1[l], v2[l], q);
        }
    }
    __syncthreads();

    // ---- per-pixel constants: nt_c = -2 t_c, tt = |t|^2 ----
    float nt0[TY], nt1[TY], nt2[TY], tt[TY], m0[TY], m1[TY];
#pragma unroll
    for (int k = 0; k < TY; k++) {
        nt0[k] = -2.f * ta[k];
        nt1[k] = -2.f * tc[k];
        nt2[k] = -2.f * te[k];
        tt[k]  = fmaf(te[k], te[k], fmaf(tc[k], tc[k], ta[k] * ta[k]));
        m0[k] = CUDART_INF_F;
        m1[k] = CUDART_INF_F;
    }

    // Flat base: iteration i -> dj = i/NR, r = i%NR, word offset r*SH_W + dj.
    const float4* base = &s4[ty * TY][tx];
#define OFF(i) (((i) % NR) * SH_W + ((i) / NR))

    float4 buf[3];
    buf[0] = base[OFF(0)];
    buf[1] = base[OFF(1)];

#pragma unroll
    for (int i = 0; i < NITER; i++) {
        if (i + 2 < NITER)
            buf[(i + 2) % 3] = base[OFF(i + 2)];
        const float4 v = buf[i % 3];
        const int dj = i / NR;
        const int r  = i % NR;
#pragma unroll
        for (int k = 0; k < TY; k++) {
            const int di = r - k;
            if (di >= 0 && di < SW) {
                float e = fmaf(nt0[k], v.x,
                          fmaf(nt1[k], v.y,
                          fmaf(nt2[k], v.z, v.w)));
                if (dj & 1) m1[k] = fminf(m1[k], e);
                else        m0[k] = fminf(m0[k], e);
            }
        }
    }
#undef OFF

    float* out_b = out + b * HW_;
#pragma unroll
    for (int k = 0; k < TY; k++) {
        float m = fminf(m0[k], m1[k]);
        out_b[(ybase + k) * W_ + xg] = sqrtf(fmaxf(tt[k] + m, 0.f));
    }
}

extern "C" void kernel_launch(void* const* d_in, const int* in_sizes, int n_in,
                              void* d_out, int out_size)
{
    const float* tfm = (const float*)d_in[0];
    const float* obs = (const float*)d_in[1];
    float* out = (float*)d_out;
    (void)in_sizes; (void)n_in; (void)out_size;

    dim3 grid(W_ / TW, H_ / TH, B_);   // 16 x 16 x 4 = 1024 blocks
    dim3 block(BDIM);
    knn_min_kernel<<<grid, block>>>(tfm, obs, out);
}

// round 14
// speedup vs baseline: 1.4276x; 1.0178x over previous
#include <cuda_runtime.h>
#include <math_constants.h>

// KNN min-dist, 9x9 window, C=3, zero-padded.
// d^2 = |t|^2 + (|o|^2 - 2 t.o), q=|o|^2 in float4.w -> 3 FFMA + 1 FMNMX/shift.
// R7 mainloop (flat (dj,r) unroll, 2-deep lookahead, dual min acc) +
// MLP-batched prologue: tfm LDGs issued first, all 24 obs LDGs batched
// (one DRAM round), STS+q in a second phase. Fixed shapes: B=4,C=3,H=256,W=512.

#define BDIM 128
#define TW 32
#define TH 16
#define TY 4
#define HALO 4
#define SW 9

#define B_ 4
#define H_ 256
#define W_ 512
#define HW_ (H_*W_)

#define SH_H (TH + 2*HALO)   // 24
#define SH_W (TW + 2*HALO)   // 40
#define NR (TY + SW - 1)     // 12
#define NITER (SW * NR)      // 108
#define NELEM (SH_H * SH_W)  // 960

__global__ __launch_bounds__(BDIM, 7) void knn_min_kernel(
    const float* __restrict__ tfm, const float* __restrict__ obs,
    float* __restrict__ out)
{
    __shared__ float4 s4[SH_H][SH_W];   // (o0, o1, o2, |o|^2)

    const int b  = blockIdx.z;
    const int x0 = blockIdx.x * TW;
    const int y0 = blockIdx.y * TH;
    const int tid = threadIdx.x;
    const int tx = tid & 31;
    const int ty = tid >> 5;

    const float* obs_b = obs + b * 3 * HW_;
    const float* tfm_b = tfm + b * 3 * HW_;

    // ---- prologue: tfm LDGs first (longest dependence chain to mainloop) ----
    const int ybase = y0 + ty * TY;
    const int xg = x0 + tx;
    float ta[TY], tc[TY], te[TY];
#pragma unroll
    for (int k = 0; k < TY; k++) {
        int g = (ybase + k) * W_ + xg;
        ta[k] = tfm_b[g];
        tc[k] = tfm_b[HW_ + g];
        te[k] = tfm_b[2 * HW_ + g];
    }

    // ---- phase 1: batch ALL obs LDGs (idx = tid + l*BDIM; 960 < 8*128) ----
    float v0[8], v1[8], v2[8];
#pragma unroll
    for (int l = 0; l < 8; l++) {
        int idx = tid + l * BDIM;
        int iy = idx / SH_W;
        int ix = idx - iy * SH_W;
        int gy = y0 - HALO + iy;
        int gx = x0 - HALO + ix;
        bool ok = (idx < NELEM) & (gy >= 0) & (gy < H_) & (gx >= 0) & (gx < W_);
        int g = gy * W_ + gx;
        v0[l] = ok ? obs_b[g] : 0.f;
        v1[l] = ok ? obs_b[HW_ + g] : 0.f;
        v2[l] = ok ? obs_b[2 * HW_ + g] : 0.f;
    }
    // ---- phase 2: q + STS ----
#pragma unroll
    for (int l = 0; l < 8; l++) {
        int idx = tid + l * BDIM;
        if (idx < NELEM) {
            int iy = idx / SH_W;
            int ix = idx - iy * SH_W;
            float q = fmaf(v2[l], v2[l], fmaf(v1[l], v1[l], v0[l] * v0[l]));
            s4[iy][ix] = make_float4(v0[l], v1[l], v2[l], q);
        }
    }
    __syncthreads();

    // ---- per-pixel constants: nt_c = -2 t_c, tt = |t|^2 ----
    float nt0[TY], nt1[TY], nt2[TY], tt[TY], m0[TY], m1[TY];
#pragma unroll
    for (int k = 0; k < TY; k++) {
        nt0[k] = -2.f * ta[k];
        nt1[k] = -2.f * tc[k];
        nt2[k] = -2.f * te[k];
        tt[k]  = fmaf(te[k], te[k], fmaf(tc[k], tc[k], ta[k] * ta[k]));
        m0[k] = CUDART_INF_F;
        m1[k] = CUDART_INF_F;
    }

    // Flat base: iteration i -> dj = i/NR, r = i%NR, word offset r*SH_W + dj.
    const float4* base = &s4[ty * TY][tx];
#define OFF(i) (((i) % NR) * SH_W + ((i) / NR))

    float4 buf[3];
    buf[0] = base[OFF(0)];
    buf[1] = base[OFF(1)];

#pragma unroll
    for (int i = 0; i < NITER; i++) {
        if (i + 2 < NITER)
            buf[(i + 2) % 3] = base[OFF(i + 2)];
        const float4 v = buf[i % 3];
        const int dj = i / NR;
        const int r  = i % NR;
#pragma unroll
        for (int k = 0; k < TY; k++) {
            const int di = r - k;
            if (di >= 0 && di < SW) {
                float e = fmaf(nt0[k], v.x,
                          fmaf(nt1[k], v.y,
                          fmaf(nt2[k], v.z, v.w)));
                if (dj & 1) m1[k] = fminf(m1[k], e);
                else        m0[k] = fminf(m0[k], e);
            }
        }
    }
#undef OFF

    float* out_b = out + b * HW_;
#pragma unroll
    for (int k = 0; k < TY; k++) {
        float m = fminf(m0[k], m1[k]);
        out_b[(ybase + k) * W_ + xg] = sqrtf(fmaxf(tt[k] + m, 0.f));
    }
}

extern "C" void kernel_launch(void* const* d_in, const int* in_sizes, int n_in,
                              void* d_out, int out_size)
{
    const float* tfm = (const float*)d_in[0];
    const float* obs = (const float*)d_in[1];
    float* out = (float*)d_out;
    (void)in_sizes; (void)n_in; (void)out_size;

    dim3 grid(W_ / TW, H_ / TH, B_);   // 16 x 16 x 4 = 1024 blocks
    dim3 block(BDIM);
    knn_min_kernel<<<grid, block>>>(tfm, obs, out);
}